// round 2
// baseline (speedup 1.0000x reference)
#include <cuda_runtime.h>
#include <cstdint>

// ---------------------------------------------------------------------------
// GRU_2602750181500: bidirectional GRU, T=2048, B=32, F=H=512, fp32.
// Kernel 1: gi = x @ w_ih^T + b_ih (both dirs), fp32 FFMA2 GEMM.
// Kernel 2: persistent recurrence, 128 blocks = 2 dirs x 4 bgroups x 16 slices.
//   - w_hh slice (96x512) resident in SMEM, stride 516 (aligned, conflict-free)
//   - GEMV: 192 threads = 96 rows x 2 k-halves, 8 batches/thread, FFMA2
//   - warps 6-7 prefetch gi chunk into SMEM during GEMV
//   - cross-block sync: st.release.gpu / ld.acquire.gpu monotonic flags
// ---------------------------------------------------------------------------

#define T_ 2048
#define B_ 32
#define H_ 512
#define G_ 1536

typedef unsigned long long ull;

__device__ __forceinline__ ull pkf(float lo, float hi) {
    ull r; asm("mov.b64 %0, {%1, %2};" : "=l"(r) : "f"(lo), "f"(hi)); return r;
}
__device__ __forceinline__ void fma2(ull& d, ull a, ull b) {
    asm("fma.rn.f32x2 %0, %1, %2, %0;" : "+l"(d) : "l"(a), "l"(b));
}
__device__ __forceinline__ float2 upk(ull v) {
    float2 f; asm("mov.b64 {%0, %1}, %2;" : "=f"(f.x), "=f"(f.y) : "l"(v)); return f;
}
__device__ __forceinline__ void st_release(unsigned* p, unsigned v) {
    asm volatile("st.release.gpu.global.u32 [%0], %1;" :: "l"(p), "r"(v) : "memory");
}
__device__ __forceinline__ unsigned ld_acquire(const unsigned* p) {
    unsigned v;
    asm volatile("ld.acquire.gpu.global.u32 %0, [%1];" : "=r"(v) : "l"(p) : "memory");
    return v;
}

// Scratch (device globals: allocation-free rule).
__device__ float    g_gi[2][(size_t)T_ * B_ * G_];   // [dir][t*B+b][3H]
__device__ float    g_h[2][4][2][H_ * 8];            // [dir][bgroup][pingpong][k*8+b]
__device__ unsigned g_flags[2][4][16 * 8];           // [dir][bgroup][slice*8]

// ---------------------------------------------------------------------------
// Kernel 1: gi GEMM (unchanged from R1 — FFMA2-pipe-bound ~3ms).
// ---------------------------------------------------------------------------
__global__ void __launch_bounds__(256, 2) gi_gemm(
    const float* __restrict__ x,
    const float* __restrict__ wf, const float* __restrict__ bf,
    const float* __restrict__ wr, const float* __restrict__ br)
{
    __shared__ float Xs[8][132];
    __shared__ float Ws[8][132];

    const int tid = threadIdx.x;
    const int dir = blockIdx.z;
    const float* __restrict__ w    = dir ? wr : wf;
    const float* __restrict__ bias = dir ? br : bf;
    float* __restrict__ gi = g_gi[dir];

    const int m0 = blockIdx.y * 128;
    const int n0 = blockIdx.x * 128;

    const int lr = tid >> 1;
    const int lc = (tid & 1) * 4;

    const float* xg = x + (size_t)(m0 + lr) * 512 + lc;
    const float* wg = w + (size_t)(n0 + lr) * 512 + lc;

    const int tx = tid & 15, ty = tid >> 4;

    ull acc[8][4];
#pragma unroll
    for (int i = 0; i < 8; i++)
#pragma unroll
        for (int j = 0; j < 4; j++) acc[i][j] = 0ULL;

    float4 xa = *(const float4*)xg;
    float4 wa = *(const float4*)wg;

    for (int kt = 0; kt < 512; kt += 8) {
        Xs[lc + 0][lr] = xa.x; Xs[lc + 1][lr] = xa.y;
        Xs[lc + 2][lr] = xa.z; Xs[lc + 3][lr] = xa.w;
        Ws[lc + 0][lr] = wa.x; Ws[lc + 1][lr] = wa.y;
        Ws[lc + 2][lr] = wa.z; Ws[lc + 3][lr] = wa.w;
        __syncthreads();
        if (kt + 8 < 512) {
            xa = *(const float4*)(xg + kt + 8);
            wa = *(const float4*)(wg + kt + 8);
        }
#pragma unroll
        for (int kk = 0; kk < 8; kk++) {
            float4 a0 = *(const float4*)&Xs[kk][ty * 8];
            float4 a1 = *(const float4*)&Xs[kk][ty * 8 + 4];
            float4 b0 = *(const float4*)&Ws[kk][tx * 8];
            float4 b1 = *(const float4*)&Ws[kk][tx * 8 + 4];
            ull bq[4] = { pkf(b0.x, b0.y), pkf(b0.z, b0.w),
                          pkf(b1.x, b1.y), pkf(b1.z, b1.w) };
            float av[8] = { a0.x, a0.y, a0.z, a0.w, a1.x, a1.y, a1.z, a1.w };
#pragma unroll
            for (int i = 0; i < 8; i++) {
                ull aq = pkf(av[i], av[i]);
#pragma unroll
                for (int j = 0; j < 4; j++) fma2(acc[i][j], aq, bq[j]);
            }
        }
        __syncthreads();
    }

    float bb2[8];
#pragma unroll
    for (int j = 0; j < 8; j++) bb2[j] = bias[n0 + tx * 8 + j];
#pragma unroll
    for (int i = 0; i < 8; i++) {
        float* cp = gi + (size_t)(m0 + ty * 8 + i) * G_ + n0 + tx * 8;
#pragma unroll
        for (int j = 0; j < 4; j++) {
            float2 v = upk(acc[i][j]);
            v.x += bb2[2 * j]; v.y += bb2[2 * j + 1];
            *(float2*)(cp + 2 * j) = v;
        }
    }
}

// ---------------------------------------------------------------------------
// Kernel 2: persistent recurrence.
// ---------------------------------------------------------------------------
#define SW_STRIDE 516                       // multiple of 4 (16B-aligned rows),
                                            // r*4 mod 32 distinct per 8-thread phase
#define OFF_H    (96 * SW_STRIDE)           // 49536 floats
#define OFF_GH   (OFF_H + 512 * 8)          // 53632
#define OFF_GI   (OFF_GH + 96 * 17)         // 55264
#define SMEM_TOT (OFF_GI + 768)             // 56032 floats = 224128 B
#define SMEM_REC (SMEM_TOT * 4)

__global__ void __launch_bounds__(256, 1) gru_rec(
    const float* __restrict__ h0,
    const float* __restrict__ whh_f, const float* __restrict__ bhh_f,
    const float* __restrict__ whh_r, const float* __restrict__ bhh_r,
    float* __restrict__ out, int out_size)
{
    extern __shared__ float smem[];
    float* sw  = smem;              // [96][516]
    float* sh  = smem + OFF_H;      // [512][8]
    float* sgh = smem + OFF_GH;     // [96][17]  (cols 0-7 kh0, 8-15 kh1)
    float* sgi = smem + OFF_GI;     // [8 batch][3 gate][32]

    const int tid = threadIdx.x;
    const int bid = blockIdx.x;
    const int dir = bid >> 6;
    const int g6  = bid & 63;
    const int bg  = g6 >> 4;   // batch group 0..3
    const int sl  = g6 & 15;   // hidden slice 0..15

    const float* __restrict__ whh = dir ? whh_r : whh_f;
    const float* __restrict__ bhh = dir ? bhh_r : bhh_f;
    const float* __restrict__ gi  = g_gi[dir];
    unsigned* flags = &g_flags[dir][bg][0];
    const unsigned base = ld_acquire(flags + sl * 8);

    // Load 96 w_hh rows into SMEM (once).
    for (int idx = tid; idx < 96 * 128; idx += 256) {
        int r = idx >> 7, c4 = (idx & 127) << 2;
        int gate = r >> 5, il2 = r & 31;
        float4 v = *(const float4*)&whh[(size_t)((gate << 9) + sl * 32 + il2) * 512 + c4];
        *(float4*)&sw[r * SW_STRIDE + c4] = v;
    }

    // Epilogue mapping: b = tid>>5 (0..7 within group), il = tid&31.
    const int b  = tid >> 5;
    const int il = tid & 31;
    const int iglob = sl * 32 + il;
    const int bglob = bg * 8 + b;

    float* hbuf0 = g_h[dir][bg][0];
    float* hbuf1 = g_h[dir][bg][1];

    hbuf0[iglob * 8 + b] = h0[(size_t)(dir * B_ + bglob) * H_ + iglob];

    const float bh_r = bhh[iglob];
    const float bh_z = bhh[512 + iglob];
    const float bh_n = bhh[1024 + iglob];

    __syncthreads();
    if (tid == 0) st_release(flags + sl * 8, base + 1);

    // GEMV mapping: tid<192 -> r = tid%96, kh = tid/96 (warp-uniform kh).
    const int r   = tid % 96;
    const int kh  = tid / 96;
    const int j0  = tid - 192;   // prefetch lane for tid>=192

    const bool write_states = (out_size > T_ * B_ * 2 * H_);

    for (int s = 0; s < T_; s++) {
        const int xrow = dir ? (T_ - 1 - s) : s;

        // gi prefetch (warps 6-7): issue LDGs early, STS during GEMV phase.
        float4 gv0, gv1, gv2;
        if (tid >= 192) {
            const float* gbase = gi + ((size_t)xrow * B_ + bg * 8) * G_ + sl * 32;
#pragma unroll
            for (int i = 0; i < 3; i++) {
                int j = j0 + 64 * i;
                int b2 = j / 24, rem = j % 24, g = rem >> 3, q = rem & 7;
                float4 v = __ldcs((const float4*)(gbase + (size_t)b2 * G_ + g * 512 + q * 4));
                if (i == 0) gv0 = v; else if (i == 1) gv1 = v; else gv2 = v;
            }
        }

        // Acquire: all 16 slice blocks must have published h(s).
        if (tid < 16) {
            const unsigned target = base + 1 + (unsigned)s;
            while (ld_acquire(flags + tid * 8) < target) { }
        }
        __syncthreads();

        const float* hsrc = (s & 1) ? hbuf1 : hbuf0;
        float*       hdst = (s & 1) ? hbuf0 : hbuf1;

        // Load full h (512x8 = 16KB) into SMEM, L2-sourced.
        for (int idx = tid; idx < 1024; idx += 256)
            *(float4*)&sh[idx * 4] = __ldcg((const float4*)hsrc + idx);
        __syncthreads();

        if (tid < 192) {
            // gh partial: row r, k in [kh*256, kh*256+256), 8 batches.
            const float* wp = sw + r * SW_STRIDE + kh * 256;
            const ull*   hp = (const ull*)(sh + kh * 256 * 8);
            ull a0 = 0, a1 = 0, a2 = 0, a3 = 0;
#pragma unroll 4
            for (int k = 0; k < 256; k += 4) {
                float4 w4 = *(const float4*)(wp + k);
                {
                    ull wq = pkf(w4.x, w4.x);
                    ulonglong2 hA = *(const ulonglong2*)(hp + (size_t)(k + 0) * 4);
                    ulonglong2 hB = *(const ulonglong2*)(hp + (size_t)(k + 0) * 4 + 2);
                    fma2(a0, wq, hA.x); fma2(a1, wq, hA.y);
                    fma2(a2, wq, hB.x); fma2(a3, wq, hB.y);
                }
                {
                    ull wq = pkf(w4.y, w4.y);
                    ulonglong2 hA = *(const ulonglong2*)(hp + (size_t)(k + 1) * 4);
                    ulonglong2 hB = *(const ulonglong2*)(hp + (size_t)(k + 1) * 4 + 2);
                    fma2(a0, wq, hA.x); fma2(a1, wq, hA.y);
                    fma2(a2, wq, hB.x); fma2(a3, wq, hB.y);
                }
                {
                    ull wq = pkf(w4.z, w4.z);
                    ulonglong2 hA = *(const ulonglong2*)(hp + (size_t)(k + 2) * 4);
                    ulonglong2 hB = *(const ulonglong2*)(hp + (size_t)(k + 2) * 4 + 2);
                    fma2(a0, wq, hA.x); fma2(a1, wq, hA.y);
                    fma2(a2, wq, hB.x); fma2(a3, wq, hB.y);
                }
                {
                    ull wq = pkf(w4.w, w4.w);
                    ulonglong2 hA = *(const ulonglong2*)(hp + (size_t)(k + 3) * 4);
                    ulonglong2 hB = *(const ulonglong2*)(hp + (size_t)(k + 3) * 4 + 2);
                    fma2(a0, wq, hA.x); fma2(a1, wq, hA.y);
                    fma2(a2, wq, hB.x); fma2(a3, wq, hB.y);
                }
            }
            float* gdst = sgh + r * 17 + kh * 8;
            float2 p;
            p = upk(a0); gdst[0] = p.x; gdst[1] = p.y;
            p = upk(a1); gdst[2] = p.x; gdst[3] = p.y;
            p = upk(a2); gdst[4] = p.x; gdst[5] = p.y;
            p = upk(a3); gdst[6] = p.x; gdst[7] = p.y;
        } else {
            // Store prefetched gi into SMEM.
#pragma unroll
            for (int i = 0; i < 3; i++) {
                int j = j0 + 64 * i;
                int b2 = j / 24, rem = j % 24, g = rem >> 3, q = rem & 7;
                float4 v = (i == 0) ? gv0 : (i == 1) ? gv1 : gv2;
                *(float4*)&sgi[(b2 * 3 + g) * 32 + q * 4] = v;
            }
        }
        __syncthreads();

        // Gates + state update (256 threads: il x b).
        const float gir = sgi[(b * 3 + 0) * 32 + il];
        const float giz = sgi[(b * 3 + 1) * 32 + il];
        const float gin = sgi[(b * 3 + 2) * 32 + il];

        const float ghr = sgh[il * 17 + b]        + sgh[il * 17 + 8 + b]        + bh_r;
        const float ghz = sgh[(32 + il) * 17 + b] + sgh[(32 + il) * 17 + 8 + b] + bh_z;
        const float ghn = sgh[(64 + il) * 17 + b] + sgh[(64 + il) * 17 + 8 + b] + bh_n;
        const float hold = sh[iglob * 8 + b];

        const float rg = 1.f / (1.f + __expf(-(gir + ghr)));
        const float zg = 1.f / (1.f + __expf(-(giz + ghz)));
        const float ng = tanhf(gin + rg * ghn);
        const float hn = (1.f - zg) * ng + zg * hold;

        __stcg(&hdst[iglob * 8 + b], hn);
        __syncthreads();
        if (tid == 0) st_release(flags + sl * 8, base + 2 + (unsigned)s);

        // Off critical path: output store.
        out[((size_t)s * B_ + bglob) * (2 * H_) + dir * H_ + iglob] = hn;
        if (write_states && s == T_ - 1)
            out[(size_t)T_ * B_ * 2 * H_ + (size_t)(dir * B_ + bglob) * H_ + iglob] = hn;
    }
}

// ---------------------------------------------------------------------------
extern "C" void kernel_launch(void* const* d_in, const int* in_sizes, int n_in,
                              void* d_out, int out_size)
{
    const float* x    = (const float*)d_in[0];
    const float* h0   = (const float*)d_in[1];
    const float* wihf = (const float*)d_in[2];
    const float* bihf = (const float*)d_in[3];
    const float* whhf = (const float*)d_in[4];
    const float* bhhf = (const float*)d_in[5];
    const float* wihr = (const float*)d_in[6];
    const float* bihr = (const float*)d_in[7];
    const float* whhr = (const float*)d_in[8];
    const float* bhhr = (const float*)d_in[9];
    float* out = (float*)d_out;

    cudaFuncSetAttribute(gru_rec, cudaFuncAttributeMaxDynamicSharedMemorySize, SMEM_REC);

    dim3 g1(G_ / 128, (T_ * B_) / 128, 2);
    gi_gemm<<<g1, 256>>>(x, wihf, bihf, wihr, bihr);

    gru_rec<<<128, 256, SMEM_REC>>>(h0, whhf, bhhf, whhr, bhhr, out, out_size);
}

// round 3
// speedup vs baseline: 1.4711x; 1.4711x over previous
#include <cuda_runtime.h>
#include <cstdint>

// ---------------------------------------------------------------------------
// GRU_2602750181500: bidirectional GRU, T=2048, B=32, F=H=512, fp32.
// Kernel 1: gi = x @ w_ih^T + b_ih (both dirs), fp32 FFMA2 GEMM.
// Kernel 2: persistent recurrence, 128 blocks = 2 dirs x 4 bgroups x 16 slices.
//   R3: R2's lean GEMV + gi prefetch, with R1's proven volatile+fence+nanosleep
//       sync restored (R2's tight ld.acquire spin regressed 2uS/step).
// ---------------------------------------------------------------------------

#define T_ 2048
#define B_ 32
#define H_ 512
#define G_ 1536

typedef unsigned long long ull;

__device__ __forceinline__ ull pkf(float lo, float hi) {
    ull r; asm("mov.b64 %0, {%1, %2};" : "=l"(r) : "f"(lo), "f"(hi)); return r;
}
__device__ __forceinline__ void fma2(ull& d, ull a, ull b) {
    asm("fma.rn.f32x2 %0, %1, %2, %0;" : "+l"(d) : "l"(a), "l"(b));
}
__device__ __forceinline__ float2 upk(ull v) {
    float2 f; asm("mov.b64 {%0, %1}, %2;" : "=f"(f.x), "=f"(f.y) : "l"(v)); return f;
}

// Scratch (device globals: allocation-free rule).
__device__ float    g_gi[2][(size_t)T_ * B_ * G_];   // [dir][t*B+b][3H]
__device__ float    g_h[2][4][2][H_ * 8];            // [dir][bgroup][pingpong][k*8+b]
__device__ unsigned g_flags[2][4][16 * 8];           // [dir][bgroup][slice*8]

// ---------------------------------------------------------------------------
// Kernel 1: gi GEMM (FFMA2, unchanged).
// ---------------------------------------------------------------------------
__global__ void __launch_bounds__(256, 2) gi_gemm(
    const float* __restrict__ x,
    const float* __restrict__ wf, const float* __restrict__ bf,
    const float* __restrict__ wr, const float* __restrict__ br)
{
    __shared__ float Xs[8][132];
    __shared__ float Ws[8][132];

    const int tid = threadIdx.x;
    const int dir = blockIdx.z;
    const float* __restrict__ w    = dir ? wr : wf;
    const float* __restrict__ bias = dir ? br : bf;
    float* __restrict__ gi = g_gi[dir];

    const int m0 = blockIdx.y * 128;
    const int n0 = blockIdx.x * 128;

    const int lr = tid >> 1;
    const int lc = (tid & 1) * 4;

    const float* xg = x + (size_t)(m0 + lr) * 512 + lc;
    const float* wg = w + (size_t)(n0 + lr) * 512 + lc;

    const int tx = tid & 15, ty = tid >> 4;

    ull acc[8][4];
#pragma unroll
    for (int i = 0; i < 8; i++)
#pragma unroll
        for (int j = 0; j < 4; j++) acc[i][j] = 0ULL;

    float4 xa = *(const float4*)xg;
    float4 wa = *(const float4*)wg;

    for (int kt = 0; kt < 512; kt += 8) {
        Xs[lc + 0][lr] = xa.x; Xs[lc + 1][lr] = xa.y;
        Xs[lc + 2][lr] = xa.z; Xs[lc + 3][lr] = xa.w;
        Ws[lc + 0][lr] = wa.x; Ws[lc + 1][lr] = wa.y;
        Ws[lc + 2][lr] = wa.z; Ws[lc + 3][lr] = wa.w;
        __syncthreads();
        if (kt + 8 < 512) {
            xa = *(const float4*)(xg + kt + 8);
            wa = *(const float4*)(wg + kt + 8);
        }
#pragma unroll
        for (int kk = 0; kk < 8; kk++) {
            float4 a0 = *(const float4*)&Xs[kk][ty * 8];
            float4 a1 = *(const float4*)&Xs[kk][ty * 8 + 4];
            float4 b0 = *(const float4*)&Ws[kk][tx * 8];
            float4 b1 = *(const float4*)&Ws[kk][tx * 8 + 4];
            ull bq[4] = { pkf(b0.x, b0.y), pkf(b0.z, b0.w),
                          pkf(b1.x, b1.y), pkf(b1.z, b1.w) };
            float av[8] = { a0.x, a0.y, a0.z, a0.w, a1.x, a1.y, a1.z, a1.w };
#pragma unroll
            for (int i = 0; i < 8; i++) {
                ull aq = pkf(av[i], av[i]);
#pragma unroll
                for (int j = 0; j < 4; j++) fma2(acc[i][j], aq, bq[j]);
            }
        }
        __syncthreads();
    }

    float bb2[8];
#pragma unroll
    for (int j = 0; j < 8; j++) bb2[j] = bias[n0 + tx * 8 + j];
#pragma unroll
    for (int i = 0; i < 8; i++) {
        float* cp = gi + (size_t)(m0 + ty * 8 + i) * G_ + n0 + tx * 8;
#pragma unroll
        for (int j = 0; j < 4; j++) {
            float2 v = upk(acc[i][j]);
            v.x += bb2[2 * j]; v.y += bb2[2 * j + 1];
            *(float2*)(cp + 2 * j) = v;
        }
    }
}

// ---------------------------------------------------------------------------
// Kernel 2: persistent recurrence.
// ---------------------------------------------------------------------------
#define SW_STRIDE 516
#define OFF_H    (96 * SW_STRIDE)
#define OFF_GH   (OFF_H + 512 * 8)
#define OFF_GI   (OFF_GH + 96 * 17)
#define SMEM_TOT (OFF_GI + 768)
#define SMEM_REC (SMEM_TOT * 4)

__global__ void __launch_bounds__(256, 1) gru_rec(
    const float* __restrict__ h0,
    const float* __restrict__ whh_f, const float* __restrict__ bhh_f,
    const float* __restrict__ whh_r, const float* __restrict__ bhh_r,
    float* __restrict__ out, int out_size)
{
    extern __shared__ float smem[];
    float* sw  = smem;              // [96][516]
    float* sh  = smem + OFF_H;      // [512][8]
    float* sgh = smem + OFF_GH;     // [96][17]
    float* sgi = smem + OFF_GI;     // [8 batch][3 gate][32]

    const int tid = threadIdx.x;
    const int bid = blockIdx.x;
    const int dir = bid >> 6;
    const int g6  = bid & 63;
    const int bg  = g6 >> 4;
    const int sl  = g6 & 15;

    const float* __restrict__ whh = dir ? whh_r : whh_f;
    const float* __restrict__ bhh = dir ? bhh_r : bhh_f;
    const float* __restrict__ gi  = g_gi[dir];
    volatile unsigned* flags = &g_flags[dir][bg][0];
    const unsigned base = flags[sl * 8];

    // Load 96 w_hh rows into SMEM (once).
    for (int idx = tid; idx < 96 * 128; idx += 256) {
        int r = idx >> 7, c4 = (idx & 127) << 2;
        int gate = r >> 5, il2 = r & 31;
        float4 v = *(const float4*)&whh[(size_t)((gate << 9) + sl * 32 + il2) * 512 + c4];
        *(float4*)&sw[r * SW_STRIDE + c4] = v;
    }

    const int b  = tid >> 5;
    const int il = tid & 31;
    const int iglob = sl * 32 + il;
    const int bglob = bg * 8 + b;

    float* hbuf0 = g_h[dir][bg][0];
    float* hbuf1 = g_h[dir][bg][1];

    hbuf0[iglob * 8 + b] = h0[(size_t)(dir * B_ + bglob) * H_ + iglob];

    const float bh_r = bhh[iglob];
    const float bh_z = bhh[512 + iglob];
    const float bh_n = bhh[1024 + iglob];

    __syncthreads();
    __threadfence();
    if (tid == 0) flags[sl * 8] = base + 1;

    // GEMV mapping: tid<192 -> r = tid%96, kh = tid/96 (warp-uniform kh).
    const int r   = tid % 96;
    const int kh  = tid / 96;
    const int j0  = tid - 192;

    const bool write_states = (out_size > T_ * B_ * 2 * H_);

    for (int s = 0; s < T_; s++) {
        const int xrow = dir ? (T_ - 1 - s) : s;

        // gi prefetch (warps 6-7): issue LDGs early; STS during GEMV phase.
        float4 gv0, gv1, gv2;
        if (tid >= 192) {
            const float* gbase = gi + ((size_t)xrow * B_ + bg * 8) * G_ + sl * 32;
#pragma unroll
            for (int i = 0; i < 3; i++) {
                int j = j0 + 64 * i;
                int b2 = j / 24, rem = j % 24, g = rem >> 3, q = rem & 7;
                float4 v = __ldcs((const float4*)(gbase + (size_t)b2 * G_ + g * 512 + q * 4));
                if (i == 0) gv0 = v; else if (i == 1) gv1 = v; else gv2 = v;
            }
        }

        // Acquire (R1-style: volatile poll + nanosleep backoff).
        if (tid < 16) {
            const unsigned target = base + 1 + (unsigned)s;
            while (flags[tid * 8] < target) __nanosleep(40);
        }
        __syncthreads();
        __threadfence();

        const float* hsrc = (s & 1) ? hbuf1 : hbuf0;
        float*       hdst = (s & 1) ? hbuf0 : hbuf1;

        // Load full h (512x8 = 16KB) into SMEM, L2-sourced.
        for (int idx = tid; idx < 1024; idx += 256)
            *(float4*)&sh[idx * 4] = __ldcg((const float4*)hsrc + idx);
        __syncthreads();

        if (tid < 192) {
            const float* wp = sw + r * SW_STRIDE + kh * 256;
            const ull*   hp = (const ull*)(sh + kh * 256 * 8);
            ull a0 = 0, a1 = 0, a2 = 0, a3 = 0;
#pragma unroll 2
            for (int k = 0; k < 256; k += 4) {
                float4 w4 = *(const float4*)(wp + k);
                {
                    ull wq = pkf(w4.x, w4.x);
                    ulonglong2 hA = *(const ulonglong2*)(hp + (size_t)(k + 0) * 4);
                    ulonglong2 hB = *(const ulonglong2*)(hp + (size_t)(k + 0) * 4 + 2);
                    fma2(a0, wq, hA.x); fma2(a1, wq, hA.y);
                    fma2(a2, wq, hB.x); fma2(a3, wq, hB.y);
                }
                {
                    ull wq = pkf(w4.y, w4.y);
                    ulonglong2 hA = *(const ulonglong2*)(hp + (size_t)(k + 1) * 4);
                    ulonglong2 hB = *(const ulonglong2*)(hp + (size_t)(k + 1) * 4 + 2);
                    fma2(a0, wq, hA.x); fma2(a1, wq, hA.y);
                    fma2(a2, wq, hB.x); fma2(a3, wq, hB.y);
                }
                {
                    ull wq = pkf(w4.z, w4.z);
                    ulonglong2 hA = *(const ulonglong2*)(hp + (size_t)(k + 2) * 4);
                    ulonglong2 hB = *(const ulonglong2*)(hp + (size_t)(k + 2) * 4 + 2);
                    fma2(a0, wq, hA.x); fma2(a1, wq, hA.y);
                    fma2(a2, wq, hB.x); fma2(a3, wq, hB.y);
                }
                {
                    ull wq = pkf(w4.w, w4.w);
                    ulonglong2 hA = *(const ulonglong2*)(hp + (size_t)(k + 3) * 4);
                    ulonglong2 hB = *(const ulonglong2*)(hp + (size_t)(k + 3) * 4 + 2);
                    fma2(a0, wq, hA.x); fma2(a1, wq, hA.y);
                    fma2(a2, wq, hB.x); fma2(a3, wq, hB.y);
                }
            }
            float* gdst = sgh + r * 17 + kh * 8;
            float2 p;
            p = upk(a0); gdst[0] = p.x; gdst[1] = p.y;
            p = upk(a1); gdst[2] = p.x; gdst[3] = p.y;
            p = upk(a2); gdst[4] = p.x; gdst[5] = p.y;
            p = upk(a3); gdst[6] = p.x; gdst[7] = p.y;
        } else {
#pragma unroll
            for (int i = 0; i < 3; i++) {
                int j = j0 + 64 * i;
                int b2 = j / 24, rem = j % 24, g = rem >> 3, q = rem & 7;
                float4 v = (i == 0) ? gv0 : (i == 1) ? gv1 : gv2;
                *(float4*)&sgi[(b2 * 3 + g) * 32 + q * 4] = v;
            }
        }
        __syncthreads();

        // Gates + state update.
        const float gir = sgi[(b * 3 + 0) * 32 + il];
        const float giz = sgi[(b * 3 + 1) * 32 + il];
        const float gin = sgi[(b * 3 + 2) * 32 + il];

        const float ghr = sgh[il * 17 + b]        + sgh[il * 17 + 8 + b]        + bh_r;
        const float ghz = sgh[(32 + il) * 17 + b] + sgh[(32 + il) * 17 + 8 + b] + bh_z;
        const float ghn = sgh[(64 + il) * 17 + b] + sgh[(64 + il) * 17 + 8 + b] + bh_n;
        const float hold = sh[iglob * 8 + b];

        const float rg = 1.f / (1.f + __expf(-(gir + ghr)));
        const float zg = 1.f / (1.f + __expf(-(giz + ghz)));
        const float ng = tanhf(gin + rg * ghn);
        const float hn = (1.f - zg) * ng + zg * hold;

        __stcg(&hdst[iglob * 8 + b], hn);
        __syncthreads();
        __threadfence();
        if (tid == 0) flags[sl * 8] = base + 2 + (unsigned)s;

        // Off critical path: output store.
        out[((size_t)s * B_ + bglob) * (2 * H_) + dir * H_ + iglob] = hn;
        if (write_states && s == T_ - 1)
            out[(size_t)T_ * B_ * 2 * H_ + (size_t)(dir * B_ + bglob) * H_ + iglob] = hn;
    }
}

// ---------------------------------------------------------------------------
extern "C" void kernel_launch(void* const* d_in, const int* in_sizes, int n_in,
                              void* d_out, int out_size)
{
    const float* x    = (const float*)d_in[0];
    const float* h0   = (const float*)d_in[1];
    const float* wihf = (const float*)d_in[2];
    const float* bihf = (const float*)d_in[3];
    const float* whhf = (const float*)d_in[4];
    const float* bhhf = (const float*)d_in[5];
    const float* wihr = (const float*)d_in[6];
    const float* bihr = (const float*)d_in[7];
    const float* whhr = (const float*)d_in[8];
    const float* bhhr = (const float*)d_in[9];
    float* out = (float*)d_out;

    cudaFuncSetAttribute(gru_rec, cudaFuncAttributeMaxDynamicSharedMemorySize, SMEM_REC);

    dim3 g1(G_ / 128, (T_ * B_) / 128, 2);
    gi_gemm<<<g1, 256>>>(x, wihf, bihf, wihr, bihr);

    gru_rec<<<128, 256, SMEM_REC>>>(h0, whhf, bhhf, whhr, bhhr, out, out_size);
}